// round 17
// baseline (speedup 1.0000x reference)
#include <cuda_runtime.h>
#include <cuda_bf16.h>

// SOM forward (SIZE = (128,128,256), B = 4096), fp32 in, fp32 coords out.
// bf16 mma.sync filter GEMM (ldmatrix) + warp-per-row exact fp32 rescore.
// NOTE: harness targets sm_100 (no 'a'): tcgen05/TMEM unavailable.
#define F_DIM 256
#define M_TOTAL 16384
#define B_MAX 4096

#define BM 128
#define BN 128
#define KC 32                 // k-chunk (bf16) staged in smem
#define KCP 40                // 80B rows: 16B-aligned (ldmatrix-legal), conflict-free
#define NCBLK (M_TOTAL / BN)  // 128 column tiles

#define MARGIN 4.0f           // > worst-case two-sided bf16 dot error (~2.6)

__device__ float g_wsq[M_TOTAL];
__device__ __nv_bfloat16 g_xb[B_MAX * F_DIM];
__device__ __nv_bfloat16 g_wb[M_TOTAL * F_DIM];
// per (row, tile): top-2 packed keys (float_key(score)<<32 | global_col)
__device__ unsigned long long g_top2[B_MAX * NCBLK * 2];

// Monotone float <-> uint order maps (no NaNs in this workload)
__device__ __forceinline__ unsigned int float_key(float s) {
    unsigned int b = __float_as_uint(s);
    return b ^ ((b & 0x80000000u) ? 0xFFFFFFFFu : 0x80000000u);
}
__device__ __forceinline__ float unkey(unsigned int k) {
    return __uint_as_float((k & 0x80000000u) ? (k ^ 0x80000000u) : ~k);
}
__device__ __forceinline__ void top2_ins(unsigned long long& k1,
                                         unsigned long long& k2,
                                         unsigned long long a) {
    if (a < k1) { k2 = k1; k1 = a; }
    else if (a < k2) { k2 = a; }
}
__device__ __forceinline__ void ldsm_x4(unsigned int& r0, unsigned int& r1,
                                        unsigned int& r2, unsigned int& r3,
                                        unsigned int addr) {
    asm volatile("ldmatrix.sync.aligned.m8n8.x4.shared.b16 {%0,%1,%2,%3}, [%4];"
                 : "=r"(r0), "=r"(r1), "=r"(r2), "=r"(r3) : "r"(addr));
}

// ---------------------------------------------------------------------------
// Fused conversion kernel.
//   blocks [0, 2048)   : w -> bf16 + exact fp32 wsq (one warp per codebook row)
//   blocks [2048, 3072): x -> bf16 (one float4 per thread)
// ---------------------------------------------------------------------------
__global__ void som_conv_kernel(const float* __restrict__ x,
                                const float* __restrict__ w) {
    if (blockIdx.x < 2048) {
        int row  = (blockIdx.x * 256 + threadIdx.x) >> 5;
        int lane = threadIdx.x & 31;
        const float4* p = reinterpret_cast<const float4*>(w + (size_t)row * F_DIM);
        float s = 0.f;
        #pragma unroll
        for (int c = lane; c < F_DIM / 4; c += 32) {
            float4 v = p[c];
            s += v.x * v.x + v.y * v.y + v.z * v.z + v.w * v.w;
            __nv_bfloat162 p0 = __floats2bfloat162_rn(v.x, v.y);
            __nv_bfloat162 p1 = __floats2bfloat162_rn(v.z, v.w);
            uint2 st = make_uint2(*reinterpret_cast<unsigned int*>(&p0),
                                  *reinterpret_cast<unsigned int*>(&p1));
            *reinterpret_cast<uint2*>(&g_wb[(size_t)row * F_DIM + c * 4]) = st;
        }
        #pragma unroll
        for (int off = 16; off; off >>= 1) s += __shfl_down_sync(0xffffffffu, s, off);
        if (lane == 0) g_wsq[row] = s;
    } else {
        int i = (blockIdx.x - 2048) * 256 + threadIdx.x;   // < 262144 float4s
        float4 v = reinterpret_cast<const float4*>(x)[i];
        __nv_bfloat162 p0 = __floats2bfloat162_rn(v.x, v.y);
        __nv_bfloat162 p1 = __floats2bfloat162_rn(v.z, v.w);
        uint2 st = make_uint2(*reinterpret_cast<unsigned int*>(&p0),
                              *reinterpret_cast<unsigned int*>(&p1));
        *reinterpret_cast<uint2*>(&g_xb[i * 4]) = st;
    }
}

// ---------------------------------------------------------------------------
// bf16 tensor GEMM + per-(row,tile) top-2 epilogue (UNCHANGED from R16 pass).
// ---------------------------------------------------------------------------
__global__ __launch_bounds__(256, 2)
void som_bf16_kernel() {
    __shared__ __align__(16) __nv_bfloat16 As[2][BM][KCP];
    __shared__ __align__(16) __nv_bfloat16 Bs[2][BN][KCP];
    __shared__ unsigned long long stop2[BM][4][2];

    const int tid  = threadIdx.x;
    const int bx   = blockIdx.x;
    const int by   = blockIdx.y;
    const int wid  = tid >> 5;
    const int lane = tid & 31;
    const int warp_m = wid & 1;
    const int warp_n = wid >> 1;
    const int m_base = warp_m * 64;
    const int n_base = warp_n * 32;
    const int lg = lane >> 2;
    const int lt = lane & 3;

    const int a_row  = lane & 15;
    const int a_koff = (lane >> 4) << 3;
    const int b_nrow = ((lane >> 4) << 3) + (lane & 7);
    const int b_koff = ((lane >> 3) & 1) << 3;

    const int r0 = tid >> 2;
    const int q0 = tid & 3;
    const __nv_bfloat16* xg0 = g_xb + (size_t)(by * BM + r0)      * F_DIM + q0 * 8;
    const __nv_bfloat16* xg1 = g_xb + (size_t)(by * BM + r0 + 64) * F_DIM + q0 * 8;
    const __nv_bfloat16* wg0 = g_wb + (size_t)(bx * BN + r0)      * F_DIM + q0 * 8;
    const __nv_bfloat16* wg1 = g_wb + (size_t)(bx * BN + r0 + 64) * F_DIM + q0 * 8;

    float acc[4][4][4];
    #pragma unroll
    for (int mt = 0; mt < 4; mt++)
        #pragma unroll
        for (int nt = 0; nt < 4; nt++)
            #pragma unroll
            for (int r = 0; r < 4; r++) acc[mt][nt][r] = 0.f;

    auto st8 = [&](__nv_bfloat16* dst, uint4 v) {
        *reinterpret_cast<uint4*>(dst) = v;
    };

    {
        uint4 a0 = *reinterpret_cast<const uint4*>(xg0);
        uint4 a1 = *reinterpret_cast<const uint4*>(xg1);
        uint4 b0 = *reinterpret_cast<const uint4*>(wg0);
        uint4 b1 = *reinterpret_cast<const uint4*>(wg1);
        st8(&As[0][r0     ][q0 * 8], a0);
        st8(&As[0][r0 + 64][q0 * 8], a1);
        st8(&Bs[0][r0     ][q0 * 8], b0);
        st8(&Bs[0][r0 + 64][q0 * 8], b1);
    }
    __syncthreads();

    const int NKC = F_DIM / KC;
    for (int kt = 0; kt < NKC; kt++) {
        const int cur = kt & 1;
        uint4 pa0, pa1, pb0, pb1;
        if (kt < NKC - 1) {
            pa0 = *reinterpret_cast<const uint4*>(xg0 + (kt + 1) * KC);
            pa1 = *reinterpret_cast<const uint4*>(xg1 + (kt + 1) * KC);
            pb0 = *reinterpret_cast<const uint4*>(wg0 + (kt + 1) * KC);
            pb1 = *reinterpret_cast<const uint4*>(wg1 + (kt + 1) * KC);
        }
        #pragma unroll
        for (int ks = 0; ks < KC; ks += 16) {
            unsigned int afr[4][4];
            #pragma unroll
            for (int mt = 0; mt < 4; mt++) {
                unsigned int addr = (unsigned int)__cvta_generic_to_shared(
                    &As[cur][m_base + mt * 16 + a_row][ks + a_koff]);
                ldsm_x4(afr[mt][0], afr[mt][1], afr[mt][2], afr[mt][3], addr);
            }
            unsigned int bfr[4][2];
            #pragma unroll
            for (int p = 0; p < 2; p++) {
                unsigned int addr = (unsigned int)__cvta_generic_to_shared(
                    &Bs[cur][n_base + p * 16 + b_nrow][ks + b_koff]);
                ldsm_x4(bfr[2 * p][0], bfr[2 * p][1],
                        bfr[2 * p + 1][0], bfr[2 * p + 1][1], addr);
            }
            #pragma unroll
            for (int mt = 0; mt < 4; mt++)
                #pragma unroll
                for (int nt = 0; nt < 4; nt++) {
                    asm volatile(
                        "mma.sync.aligned.m16n8k16.row.col.f32.bf16.bf16.f32 "
                        "{%0,%1,%2,%3}, {%4,%5,%6,%7}, {%8,%9}, {%0,%1,%2,%3};\n"
                        : "+f"(acc[mt][nt][0]), "+f"(acc[mt][nt][1]),
                          "+f"(acc[mt][nt][2]), "+f"(acc[mt][nt][3])
                        : "r"(afr[mt][0]), "r"(afr[mt][1]),
                          "r"(afr[mt][2]), "r"(afr[mt][3]),
                          "r"(bfr[nt][0]), "r"(bfr[nt][1]));
                }
        }
        if (kt < NKC - 1) {
            const int nxt = cur ^ 1;
            st8(&As[nxt][r0     ][q0 * 8], pa0);
            st8(&As[nxt][r0 + 64][q0 * 8], pa1);
            st8(&Bs[nxt][r0     ][q0 * 8], pb0);
            st8(&Bs[nxt][r0 + 64][q0 * 8], pb1);
            __syncthreads();
        }
    }

    #pragma unroll
    for (int mt = 0; mt < 4; mt++) {
        #pragma unroll
        for (int h = 0; h < 2; h++) {
            int row_local = m_base + mt * 16 + lg + h * 8;
            unsigned long long k1 = ~0ull, k2 = ~0ull;
            #pragma unroll
            for (int nt = 0; nt < 4; nt++) {
                #pragma unroll
                for (int j = 0; j < 2; j++) {
                    int col = bx * BN + n_base + nt * 8 + 2 * lt + j;
                    float s = g_wsq[col] - 2.f * acc[mt][nt][h * 2 + j];
                    unsigned long long key =
                        ((unsigned long long)float_key(s) << 32) | (unsigned int)col;
                    top2_ins(k1, k2, key);
                }
            }
            #pragma unroll
            for (int off = 1; off <= 2; off <<= 1) {
                unsigned long long o1 = __shfl_xor_sync(0xffffffffu, k1, off);
                unsigned long long o2 = __shfl_xor_sync(0xffffffffu, k2, off);
                top2_ins(k1, k2, o1);
                top2_ins(k1, k2, o2);
            }
            if (lt == 0) {
                stop2[row_local][warp_n][0] = k1;
                stop2[row_local][warp_n][1] = k2;
            }
        }
    }
    __syncthreads();

    if (tid < BM) {
        unsigned long long k1 = stop2[tid][0][0], k2 = stop2[tid][0][1];
        #pragma unroll
        for (int wn = 1; wn < 4; wn++) {
            top2_ins(k1, k2, stop2[tid][wn][0]);
            top2_ins(k1, k2, stop2[tid][wn][1]);
        }
        const int grow = by * BM + tid;
        g_top2[((size_t)grow * NCBLK + bx) * 2 + 0] = k1;
        g_top2[((size_t)grow * NCBLK + bx) * 2 + 1] = k2;
    }
}

// ---------------------------------------------------------------------------
// Rescore: ONE WARP PER ROW (no smem, no block barriers, no atomics).
// Lane l owns tiles 4l..4l+3 (8 keys, 4x ldg.128). Warp shfl-min -> margin
// threshold -> ballot-walk candidates -> warp-cooperative exact fp32 dots.
// All reductions xor-based so every lane holds identical state (determinism).
// ---------------------------------------------------------------------------
__global__ void som_rescore_kernel(const float* __restrict__ x,
                                   const float* __restrict__ w,
                                   float* __restrict__ out) {
    const int row  = (blockIdx.x * blockDim.x + threadIdx.x) >> 5;
    const int lane = threadIdx.x & 31;

    // load my 8 keys (tiles 4*lane .. 4*lane+3)
    const unsigned long long* kp =
        g_top2 + (size_t)row * NCBLK * 2 + (size_t)lane * 8;
    unsigned long long k[8];
    #pragma unroll
    for (int i = 0; i < 4; i++) {
        ulonglong2 v = reinterpret_cast<const ulonglong2*>(kp)[i];
        k[2 * i] = v.x; k[2 * i + 1] = v.y;
    }

    // warp-wide approx min (k1 entries only need considering, but including
    // k2 entries cannot change the min since k1 <= k2 per tile)
    unsigned long long gmin = k[0];
    #pragma unroll
    for (int i = 1; i < 8; i++) gmin = k[i] < gmin ? k[i] : gmin;
    #pragma unroll
    for (int off = 16; off; off >>= 1) {
        unsigned long long o = __shfl_xor_sync(0xffffffffu, gmin, off);
        gmin = o < gmin ? o : gmin;
    }
    const unsigned int kthresh =
        float_key(unkey((unsigned int)(gmin >> 32)) + MARGIN);

    // stage x row in registers: xr[i] = x[row][lane + 32i]
    float xr[8];
    #pragma unroll
    for (int i = 0; i < 8; i++)
        xr[i] = x[(size_t)row * F_DIM + lane + 32 * i];

    unsigned long long best = ~0ull;   // identical on all lanes throughout

    #pragma unroll
    for (int i = 0; i < 4; i++) {
        const bool full = (unsigned int)(k[2 * i + 1] >> 32) < kthresh;
        const bool cand = !full && ((unsigned int)(k[2 * i] >> 32) < kthresh);

        // rare: full-tile exact scan (2nd-best also within margin)
        unsigned fm = __ballot_sync(0xffffffffu, full);
        while (fm) {
            int src = __ffs(fm) - 1; fm &= fm - 1;
            int tile = src * 4 + i;
            for (int c = 0; c < BN; c++) {
                int col = tile * BN + c;
                const float* wr = w + (size_t)col * F_DIM;
                float p = 0.f;
                #pragma unroll
                for (int j = 0; j < 8; j++) p += xr[j] * wr[lane + 32 * j];
                #pragma unroll
                for (int off = 16; off; off >>= 1)
                    p += __shfl_xor_sync(0xffffffffu, p, off);
                float s = g_wsq[col] - 2.f * p;
                unsigned long long key =
                    ((unsigned long long)float_key(s) << 32) | (unsigned int)col;
                best = key < best ? key : best;
            }
        }

        // common: single candidate per flagged tile
        unsigned cm = __ballot_sync(0xffffffffu, cand);
        while (cm) {
            int src = __ffs(cm) - 1; cm &= cm - 1;
            int col = (int)(__shfl_sync(0xffffffffu, k[2 * i], src) & 0xFFFFFFFFull);
            const float* wr = w + (size_t)col * F_DIM;
            float p = 0.f;
            #pragma unroll
            for (int j = 0; j < 8; j++) p += xr[j] * wr[lane + 32 * j];
            #pragma unroll
            for (int off = 16; off; off >>= 1)
                p += __shfl_xor_sync(0xffffffffu, p, off);
            float s = g_wsq[col] - 2.f * p;
            unsigned long long key =
                ((unsigned long long)float_key(s) << 32) | (unsigned int)col;
            best = key < best ? key : best;
        }
    }

    if (lane == 0) {
        int idx = (int)(best & 0xFFFFFFFFull);
        out[row * 2 + 0] = (float)(idx >> 7);    // min_idx / 128
        out[row * 2 + 1] = (float)(idx & 127);   // min_idx % 128
    }
}

// ---------------------------------------------------------------------------
extern "C" void kernel_launch(void* const* d_in, const int* in_sizes, int n_in,
                              void* d_out, int out_size) {
    // Size-based input dispatch (xb: 1,048,576 elems; weights: 4,194,304).
    const float* xb;
    const float* w;
    int nx;
    if (in_sizes[0] <= in_sizes[1]) {
        xb = (const float*)d_in[0]; nx = in_sizes[0];
        w  = (const float*)d_in[1];
    } else {
        xb = (const float*)d_in[1]; nx = in_sizes[1];
        w  = (const float*)d_in[0];
    }
    float* out = (float*)d_out;
    const int B = nx / F_DIM;            // 4096

    som_conv_kernel<<<3072, 256>>>(xb, w);   // 2048 w-blocks + 1024 x-blocks

    dim3 grid(NCBLK, B / BM);            // (128, 32)
    som_bf16_kernel<<<grid, 256>>>();

    som_rescore_kernel<<<B / 8, 256>>>(xb, w, out);   // warp per row
}